// round 14
// baseline (speedup 1.0000x reference)
#include <cuda_runtime.h>
#include <cuda_bf16.h>
#include <cstdint>
#include <math.h>

// Problem constants: B=1, n_seq=S=256, seq_len=L=256, c_m=256, H=8, ch=32, HC=256
#define S_DIM 256
#define L_DIM 256
#define C_DIM 256
#define HC_DIM 256
#define NH 8
#define CH 32
#define NROWS (S_DIM * L_DIM)  // 65536

// ---------------------------------------------------------------------------
// Scratch (device globals per allocation rules)
// ---------------------------------------------------------------------------
__device__ __align__(16) __nv_bfloat16 g_mn_split[NROWS * 512];
__device__ __align__(16) __nv_bfloat16 g_att_split[NROWS * 512];
// Q/K/V attention-tile layout: [(l*8+h)][s][64] rows = [hi32|lo32] bf16
__device__ __align__(16) __nv_bfloat16 g_qs[NROWS * 512];
__device__ __align__(16) __nv_bfloat16 g_ks[NROWS * 512];
__device__ __align__(16) __nv_bfloat16 g_vs[NROWS * 512];
__device__ __align__(16) float g_g[NROWS * HC_DIM];
__device__ __align__(16) __nv_bfloat16 g_Bqkvg[768 * 1024];  // cols: q|k|v|g
__device__ __align__(16) __nv_bfloat16 g_Bo[768 * 256];

// ---------------------------------------------------------------------------
// Helpers
// ---------------------------------------------------------------------------
__device__ __forceinline__ uint32_t smem_u32(const void* p) {
    uint32_t a;
    asm("{ .reg .u64 t; cvta.to.shared.u64 t, %1; cvt.u32.u64 %0, t; }"
        : "=r"(a) : "l"(p));
    return a;
}

#define SWZ(o) ((o) ^ (((o) >> 3) & 0x70))

__device__ __forceinline__ void cp_async16(uint32_t saddr, const void* gptr) {
    asm volatile("cp.async.cg.shared.global [%0], [%1], 16;"
                 :: "r"(saddr), "l"(__cvta_generic_to_global(gptr)) : "memory");
}
#define CP_COMMIT() asm volatile("cp.async.commit_group;" ::: "memory")
#define CP_WAITG(n) asm volatile("cp.async.wait_group %0;" :: "n"(n) : "memory")

__device__ __forceinline__ void ldsm4(uint32_t* r, uint32_t addr) {
    asm volatile("ldmatrix.sync.aligned.m8n8.x4.shared.b16 {%0,%1,%2,%3}, [%4];"
                 : "=r"(r[0]), "=r"(r[1]), "=r"(r[2]), "=r"(r[3]) : "r"(addr));
}
__device__ __forceinline__ void ldsm4t(uint32_t* r, uint32_t addr) {
    asm volatile("ldmatrix.sync.aligned.m8n8.x4.trans.shared.b16 {%0,%1,%2,%3}, [%4];"
                 : "=r"(r[0]), "=r"(r[1]), "=r"(r[2]), "=r"(r[3]) : "r"(addr));
}
__device__ __forceinline__ void mma_bf16(float* c, const uint32_t* a,
                                         uint32_t b0, uint32_t b1) {
    asm volatile(
        "mma.sync.aligned.m16n8k16.row.col.f32.bf16.bf16.f32 "
        "{%0,%1,%2,%3}, {%4,%5,%6,%7}, {%8,%9}, {%0,%1,%2,%3};"
        : "+f"(c[0]), "+f"(c[1]), "+f"(c[2]), "+f"(c[3])
        : "r"(a[0]), "r"(a[1]), "r"(a[2]), "r"(a[3]), "r"(b0), "r"(b1));
}

// fp32 -> bf16 hi/lo split (packed pairs), bit-trick hi reconstruction.
__device__ __forceinline__ void split2(float a, float b, uint32_t& h, uint32_t& l) {
    uint32_t hb;
    asm("cvt.rn.bf16x2.f32 %0, %1, %2;" : "=r"(hb) : "f"(b), "f"(a));
    const float fa = __uint_as_float(hb << 16);
    const float fb = __uint_as_float(hb & 0xffff0000u);
    const float la = a - fa;
    const float lb = b - fb;
    uint32_t lo;
    asm("cvt.rn.bf16x2.f32 %0, %1, %2;" : "=r"(lo) : "f"(lb), "f"(la));
    h = hb;
    l = lo;
}

// ---------------------------------------------------------------------------
// LayerNorm -> split bf16 [row][512]. One warp per row.
// ---------------------------------------------------------------------------
__global__ __launch_bounds__(256) void ln_kernel(
    const float* __restrict__ m, const float* __restrict__ w,
    const float* __restrict__ b, __nv_bfloat16* __restrict__ osplit)
{
    const int warp = threadIdx.x >> 5;
    const int lane = threadIdx.x & 31;
    const int row  = blockIdx.x * 8 + warp;

    const float4* x4 = (const float4*)(m + (size_t)row * C_DIM);
    float4 v0 = x4[lane * 2 + 0];
    float4 v1 = x4[lane * 2 + 1];

    float s1 = (v0.x + v0.y) + (v0.z + v0.w) + (v1.x + v1.y) + (v1.z + v1.w);
    float s2 = v0.x * v0.x + v0.y * v0.y + v0.z * v0.z + v0.w * v0.w
             + v1.x * v1.x + v1.y * v1.y + v1.z * v1.z + v1.w * v1.w;
    #pragma unroll
    for (int o = 16; o > 0; o >>= 1) {
        s1 += __shfl_xor_sync(0xffffffffu, s1, o);
        s2 += __shfl_xor_sync(0xffffffffu, s2, o);
    }
    const float mu  = s1 * (1.0f / 256.0f);
    const float var = s2 * (1.0f / 256.0f) - mu * mu;
    const float rs  = rsqrtf(var + 1e-5f);

    const float4* w4 = (const float4*)w;
    const float4* b4 = (const float4*)b;
    float4 w0 = w4[lane * 2 + 0], w1 = w4[lane * 2 + 1];
    float4 b0 = b4[lane * 2 + 0], b1 = b4[lane * 2 + 1];

    float r[8];
    r[0] = (v0.x - mu) * rs * w0.x + b0.x;
    r[1] = (v0.y - mu) * rs * w0.y + b0.y;
    r[2] = (v0.z - mu) * rs * w0.z + b0.z;
    r[3] = (v0.w - mu) * rs * w0.w + b0.w;
    r[4] = (v1.x - mu) * rs * w1.x + b1.x;
    r[5] = (v1.y - mu) * rs * w1.y + b1.y;
    r[6] = (v1.z - mu) * rs * w1.z + b1.z;
    r[7] = (v1.w - mu) * rs * w1.w + b1.w;

    uint4 H, L;
    split2(r[0], r[1], H.x, L.x);
    split2(r[2], r[3], H.y, L.y);
    split2(r[4], r[5], H.z, L.z);
    split2(r[6], r[7], H.w, L.w);
    const size_t ofs = (size_t)row * 512 + lane * 8;
    *(uint4*)(osplit + ofs)       = H;
    *(uint4*)(osplit + ofs + 256) = L;
}

// ---------------------------------------------------------------------------
// Weight prep: B_ext[k_ext][n] with k_ext rows [hi, hi, lo] from w[k][n].
// ---------------------------------------------------------------------------
__global__ __launch_bounds__(256) void wconv_kernel(
    const float* __restrict__ w0, const float* __restrict__ w1,
    const float* __restrict__ w2, const float* __restrict__ w3,
    const float* __restrict__ w4,
    __nv_bfloat16* __restrict__ Bqkvg, __nv_bfloat16* __restrict__ Bo)
{
    const float* ws[5] = {w0, w1, w2, w3, w4};
    const int k   = blockIdx.x;        // 0..767
    const int wi  = blockIdx.y;        // 0..4
    const int n   = threadIdx.x;       // 0..255
    const int ks  = k & 255;
    const int seg = k >> 8;            // 0,1 -> hi ; 2 -> lo
    float x = ws[wi][ks * 256 + n];
    __nv_bfloat16 h = __float2bfloat16_rn(x);
    __nv_bfloat16 v = (seg < 2) ? h : __float2bfloat16_rn(x - __bfloat162float(h));
    if (wi < 4) Bqkvg[(size_t)k * 1024 + wi * 256 + n] = v;
    else        Bo[(size_t)k * 256 + n] = v;
}

// ---------------------------------------------------------------------------
// bf16 GEMM via mma.sync, templated on BM (M-tile):
//   BM=128: 128x128 tile, 64x32 warp tiles (qkvg; R11-proven config).
//   BM=64 : 64x128 tile, 32x32 warp tiles (out-proj; doubles grid to kill
//           the 3.46-wave quantization tail).
// ---------------------------------------------------------------------------
#define NSTAGE 3

template <int BM>
__device__ __forceinline__ void ld_chunk(
    uint32_t sbase, const __nv_bfloat16* __restrict__ A,
    const __nv_bfloat16* __restrict__ B, int Nb,
    size_t row0, int n0, int kb, int tid)
{
    const int a_off = (kb < 8 ? kb : kb - 8) * 64;
    #pragma unroll
    for (int t = 0; t < BM / 32; t++) {
        const int i = tid + t * 256;
        const int r = i >> 3, c8 = i & 7;
        cp_async16(sbase + SWZ((uint32_t)(r * 128 + c8 * 16)),
                   A + (row0 + r) * 512 + a_off + c8 * 8);
    }
    const uint32_t bbase = sbase + (uint32_t)(BM * 128);
    #pragma unroll
    for (int t = 0; t < 4; t++) {
        const int i = tid + t * 256;
        const int k = i >> 4, u = i & 15;
        const uint32_t sub = (u >= 8) ? 8192u : 0u;
        cp_async16(bbase + sub + SWZ((uint32_t)(k * 128 + (u & 7) * 16)),
                   B + (size_t)(kb * 64 + k) * Nb + n0 + u * 8);
    }
}

template <int BM>
__global__ __launch_bounds__(256, 2) void gemm_mma(
    const __nv_bfloat16* __restrict__ A, const __nv_bfloat16* __restrict__ B,
    int Nb, int qkv_mode,
    void* C0, void* C1, void* C2, void* C3,
    const float* bias0, const float* bias3)
{
    constexpr int IT = BM / 32;                 // 16-row warp subtiles
    constexpr int STAGE = BM * 128 + 16384;     // A + B per stage
    extern __shared__ char smem[];
    const uint32_t sb = smem_u32(smem);
    const int tid  = threadIdx.x;
    const int warp = tid >> 5, lane = tid & 31;
    const int wm = (warp >> 2) * (BM / 2);
    const int wn = (warp & 3) * 32;
    const size_t row0 = (size_t)blockIdx.y * BM;
    const int n0 = blockIdx.x * 128;

    #pragma unroll
    for (int s = 0; s < 3; s++) {
        ld_chunk<BM>(sb + s * STAGE, A, B, Nb, row0, n0, s, tid);
        CP_COMMIT();
    }

    float acc[IT][4][4];
    #pragma unroll
    for (int i = 0; i < IT; i++)
        #pragma unroll
        for (int j = 0; j < 4; j++)
            #pragma unroll
            for (int x = 0; x < 4; x++) acc[i][j][x] = 0.0f;

    const int lr  = lane & 15;
    const int lh  = lane >> 4;
    const uint32_t bsub = (wn >= 64) ? 8192u : 0u;
    const int wn2 = wn & 63;

    const uint32_t mix = (uint32_t)((lr & 7) << 4);
    uint32_t abase[IT];
    #pragma unroll
    for (int i = 0; i < IT; i++)
        abase[i] = (uint32_t)((wm + i * 16 + lr) * 128)
                   + ((uint32_t)(lh * 16) ^ mix);
    uint32_t bbase[2];
    #pragma unroll
    for (int j2 = 0; j2 < 2; j2++)
        bbase[j2] = (uint32_t)(BM * 128) + bsub + (uint32_t)(lr * 128)
                    + ((uint32_t)(wn2 * 2 + j2 * 32 + lh * 16) ^ mix);

    #pragma unroll 1
    for (int kb = 0; kb < 12; kb++) {
        CP_WAITG(2);
        __syncthreads();
        const int stg = kb % 3;
        const uint32_t sgb = sb + stg * STAGE;

        #pragma unroll
        for (int kk = 0; kk < 4; kk++) {
            uint32_t a[IT][4];
            #pragma unroll
            for (int i = 0; i < IT; i++)
                ldsm4(a[i], sgb + (abase[i] ^ (uint32_t)(kk * 32)));
            uint32_t bfr[2][4];
            #pragma unroll
            for (int j2 = 0; j2 < 2; j2++)
                ldsm4t(bfr[j2], sgb + bbase[j2] + (uint32_t)(kk * 2048));
            #pragma unroll
            for (int i = 0; i < IT; i++)
                #pragma unroll
                for (int j = 0; j < 4; j++)
                    mma_bf16(acc[i][j], a[i],
                             bfr[j >> 1][(j & 1) * 2], bfr[j >> 1][(j & 1) * 2 + 1]);
        }
        __syncthreads();
        if (kb + 3 < 12) ld_chunk<BM>(sb + stg * STAGE, A, B, Nb, row0, n0, kb + 3, tid);
        CP_COMMIT();
    }

    const int buf = (n0 >> 8) & 3;
    const int colbase = (n0 & 255) + wn + (lane & 3) * 2;

    if (BM == 128 && qkv_mode && buf < 3) {
        __nv_bfloat16* Cq = (__nv_bfloat16*)((buf == 0) ? C0 : (buf == 1) ? C1 : C2);
        const float qsc = (buf == 0) ? 0.17677669529663689f * 1.44269504088896f
                                     : 1.0f;
        #pragma unroll
        for (int i = 0; i < IT; i++) {
            const int r0 = (int)row0 + wm + i * 16 + (lane >> 2);
            #pragma unroll
            for (int j = 0; j < 4; j++) {
                const int col = colbase + j * 8;
                const int hh = col >> 5, cc = col & 31;
                #pragma unroll
                for (int rr = 0; rr < 2; rr++) {
                    const int r = r0 + rr * 8;
                    const int s = r >> 8, ll = r & 255;
                    const size_t dst = ((size_t)(ll * 8 + hh) * 256 + s) * 64 + cc;
                    uint32_t H, L;
                    split2(acc[i][j][rr * 2] * qsc, acc[i][j][rr * 2 + 1] * qsc,
                           H, L);
                    *(uint32_t*)(Cq + dst)      = H;
                    *(uint32_t*)(Cq + dst + 32) = L;
                }
            }
        }
    } else {
        float* C = (float*)((qkv_mode) ? C3 : C0);
        const float* bias = (qkv_mode) ? bias3 : bias0;
        #pragma unroll
        for (int i = 0; i < IT; i++) {
            const size_t r0 = row0 + wm + i * 16 + (lane >> 2);
            #pragma unroll
            for (int j = 0; j < 4; j++) {
                const int col = colbase + j * 8;
                float bx = 0.f, by = 0.f;
                if (bias) { bx = bias[col]; by = bias[col + 1]; }
                float2 v0 = make_float2(acc[i][j][0] + bx, acc[i][j][1] + by);
                float2 v1 = make_float2(acc[i][j][2] + bx, acc[i][j][3] + by);
                *(float2*)(C + r0 * 256 + col)       = v0;
                *(float2*)(C + (r0 + 8) * 256 + col) = v1;
            }
        }
    }
}

// ---------------------------------------------------------------------------
// Tensor-core flash attention per (l,h) tile, 512 threads / 16 warps,
// 2 CTAs/SM. Exact R10/R11 form (proven 134us; R13 chunking regressed).
//   s' = h*32 + l/8 ; l' = (l%8)*32 + s/8 ; c' = (s%8)*32 + c
// ---------------------------------------------------------------------------
#define ATT_SMEM (3 * 32768)

__global__ __launch_bounds__(512, 2) void attn_mma_kernel(
    const __nv_bfloat16* __restrict__ Qg, const __nv_bfloat16* __restrict__ Kg,
    const __nv_bfloat16* __restrict__ Vg, const float* __restrict__ Gg,
    __nv_bfloat16* __restrict__ Osplit)
{
    extern __shared__ char smem[];
    const uint32_t sb = smem_u32(smem);
    const uint32_t QS = sb, KS = sb + 32768, VS = sb + 65536;

    const int tile = blockIdx.x;
    const int l = tile >> 3, h = tile & 7;
    const int tid = threadIdx.x;
    const size_t gbase0 = (size_t)tile * 256 * 64;

    #pragma unroll
    for (int t = 0; t < 4; t++) {
        const int idx = t * 512 + tid;
        const int r = idx >> 3, j = idx & 7;
        const uint32_t so = SWZ((uint32_t)(r * 128 + j * 16));
        const size_t go = gbase0 + (size_t)r * 64 + j * 8;
        cp_async16(QS + so, Qg + go);
        cp_async16(KS + so, Kg + go);
        cp_async16(VS + so, Vg + go);
    }
    CP_COMMIT();
    CP_WAITG(0);
    __syncthreads();

    const int warp = tid >> 5, lane = tid & 31;
    const int s0 = warp * 16;
    const int lr = lane & 15, lh = lane >> 4;

    uint32_t qh[2][4], ql[2][4];
    #pragma unroll
    for (int kk = 0; kk < 2; kk++) {
        const uint32_t rowb = (uint32_t)(s0 + lr) * 128;
        ldsm4(qh[kk], QS + SWZ(rowb + (kk * 16 + lh * 8) * 2));
        ldsm4(ql[kk], QS + SWZ(rowb + (32 + kk * 16 + lh * 8) * 2));
    }

    const int klr = (lane & 7) + ((lane >> 4) << 3);
    const uint32_t mix = (uint32_t)((lane & 7) << 4);
    const uint32_t kcolb = (uint32_t)(((lane >> 3) & 1) * 16);
    uint32_t kaddr[2], vaddr[2];
    #pragma unroll
    for (int c = 0; c < 2; c++) {
        kaddr[c] = KS + (uint32_t)(klr * 128) + ((kcolb + c * 32) ^ mix);
        vaddr[c] = VS + (uint32_t)(lr * 128)
                   + (((uint32_t)(lh * 16) + c * 32) ^ mix);
    }

    float o[4][4];
    #pragma unroll
    for (int j = 0; j < 4; j++)
        #pragma unroll
        for (int x = 0; x < 4; x++) o[j][x] = 0.0f;
    float sm[2] = {0.f, 0.f};

    auto S_compute = [&](int gt, float s[2][4]) {
        const uint32_t gg = (uint32_t)(gt * 2048);
        uint32_t kh[2][4], kl[2][4];
        ldsm4(kh[0], kaddr[0] + gg);
        ldsm4(kh[1], kaddr[1] + gg);
        ldsm4(kl[0], (kaddr[0] + gg) ^ 64u);
        ldsm4(kl[1], (kaddr[1] + gg) ^ 64u);
        #pragma unroll
        for (int x = 0; x < 4; x++) { s[0][x] = 0.f; s[1][x] = 0.f; }
        #pragma unroll
        for (int ch = 0; ch < 2; ch++) {
            mma_bf16(s[0], qh[ch], kh[ch][0], kh[ch][1]);
            mma_bf16(s[1], qh[ch], kh[ch][2], kh[ch][3]);
            mma_bf16(s[0], ql[ch], kh[ch][0], kh[ch][1]);
            mma_bf16(s[1], ql[ch], kh[ch][2], kh[ch][3]);
            mma_bf16(s[0], qh[ch], kl[ch][0], kl[ch][1]);
            mma_bf16(s[1], qh[ch], kl[ch][2], kl[ch][3]);
        }
    };

    auto PV_compute = [&](int gt, float s[2][4]) {
        #pragma unroll
        for (int tgt = 0; tgt < 2; tgt++) {
            #pragma unroll
            for (int x = 0; x < 4; x++) s[tgt][x] = exp2f(s[tgt][x]);
        }
        sm[0] += (s[0][0] + s[0][1]) + (s[1][0] + s[1][1]);
        sm[1] += (s[0][2] + s[0][3]) + (s[1][2] + s[1][3]);

        uint32_t ah[4], al[4];
        split2(s[0][0], s[0][1], ah[0], al[0]);
        split2(s[0][2], s[0][3], ah[1], al[1]);
        split2(s[1][0], s[1][1], ah[2], al[2]);
        split2(s[1][2], s[1][3], ah[3], al[3]);

        const uint32_t gg = (uint32_t)(gt * 2048);
        uint32_t vh[2][4], vl[2][4];
        ldsm4t(vh[0], vaddr[0] + gg);
        ldsm4t(vh[1], vaddr[1] + gg);
        ldsm4t(vl[0], (vaddr[0] + gg) ^ 64u);
        ldsm4t(vl[1], (vaddr[1] + gg) ^ 64u);
        #pragma unroll
        for (int j = 0; j < 4; j++) {
            const int j2 = j >> 1, jj = (j & 1) * 2;
            mma_bf16(o[j], ah, vh[j2][jj], vh[j2][jj + 1]);
            mma_bf16(o[j], al, vh[j2][jj], vh[j2][jj + 1]);
            mma_bf16(o[j], ah, vl[j2][jj], vl[j2][jj + 1]);
        }
    };

    float s_a[2][4], s_b[2][4];
    S_compute(0, s_a);
    #pragma unroll
    for (int gt = 0; gt < 16; gt += 2) {
        if (gt + 1 < 16) S_compute(gt + 1, s_b);
        PV_compute(gt, s_a);
        if (gt + 2 < 16) S_compute(gt + 2, s_a);
        if (gt + 1 < 16) PV_compute(gt + 1, s_b);
    }

    // ---- epilogue: normalize, gate, scramble, store split bf16 ----
    const int i_o = h * 32 + (l >> 3);
    #pragma unroll
    for (int rr = 0; rr < 2; rr++) {
        float v = sm[rr];
        v += __shfl_xor_sync(0xffffffffu, v, 1);
        v += __shfl_xor_sync(0xffffffffu, v, 2);
        const float inv = 1.0f / v;
        const int s = s0 + (lane >> 2) + rr * 8;
        const int j_o = ((l & 7) << 5) + (s >> 3);
        const int k_o = (s & 7) << 5;
        const size_t gb = ((size_t)i_o * 256 + j_o) * 256 + k_o;
        const size_t ob = ((size_t)i_o * 256 + j_o) * 512 + k_o;
        #pragma unroll
        for (int j = 0; j < 4; j++) {
            const int c = j * 8 + (lane & 3) * 2;
            const float2 gg = *(const float2*)(Gg + gb + c);
            const float w0 = o[j][rr * 2] * inv
                             / (1.0f + exp2f(-gg.x * 1.44269504088896f));
            const float w1 = o[j][rr * 2 + 1] * inv
                             / (1.0f + exp2f(-gg.y * 1.44269504088896f));
            uint32_t H, L;
            split2(w0, w1, H, L);
            *(uint32_t*)(Osplit + ob + c)       = H;
            *(uint32_t*)(Osplit + ob + 256 + c) = L;
        }
    }
}

// ---------------------------------------------------------------------------
extern "C" void kernel_launch(void* const* d_in, const int* in_sizes, int n_in,
                              void* d_out, int out_size)
{
    const float* m    = (const float*)d_in[0];
    const float* ln_w = (const float*)d_in[1];
    const float* ln_b = (const float*)d_in[2];
    const float* wq   = (const float*)d_in[3];
    const float* wk   = (const float*)d_in[4];
    const float* wv   = (const float*)d_in[5];
    const float* wg   = (const float*)d_in[6];
    const float* bg   = (const float*)d_in[7];
    const float* wo   = (const float*)d_in[8];
    const float* bo   = (const float*)d_in[9];
    float* out = (float*)d_out;

    __nv_bfloat16 *mns, *ats, *Bq, *Bo, *qs, *ks, *vs;
    float *g;
    cudaGetSymbolAddress((void**)&mns, g_mn_split);
    cudaGetSymbolAddress((void**)&ats, g_att_split);
    cudaGetSymbolAddress((void**)&qs,  g_qs);
    cudaGetSymbolAddress((void**)&ks,  g_ks);
    cudaGetSymbolAddress((void**)&vs,  g_vs);
    cudaGetSymbolAddress((void**)&g,   g_g);
    cudaGetSymbolAddress((void**)&Bq,  g_Bqkvg);
    cudaGetSymbolAddress((void**)&Bo,  g_Bo);

    cudaFuncSetAttribute(gemm_mma<128>,
                         cudaFuncAttributeMaxDynamicSharedMemorySize,
                         NSTAGE * (128 * 128 + 16384));
    cudaFuncSetAttribute(gemm_mma<64>,
                         cudaFuncAttributeMaxDynamicSharedMemorySize,
                         NSTAGE * (64 * 128 + 16384));
    cudaFuncSetAttribute(attn_mma_kernel,
                         cudaFuncAttributeMaxDynamicSharedMemorySize, ATT_SMEM);

    // 1. LayerNorm -> split bf16
    ln_kernel<<<NROWS / 8, 256>>>(m, ln_w, ln_b, mns);

    // 2. Weight prep
    wconv_kernel<<<dim3(768, 5), 256>>>(wq, wk, wv, wg, wo, Bq, Bo);

    // 3. Fused Q/K/V/G projection: [65536,768] @ [768,1024] (BM=128)
    gemm_mma<128><<<dim3(8, NROWS / 128), 256, NSTAGE * (128 * 128 + 16384)>>>(
        mns, Bq, 1024, 1, qs, ks, vs, g, nullptr, bg);

    // 4. Tensor-core flash attention (2 CTA/SM) + gate + scramble
    attn_mma_kernel<<<L_DIM * NH, 512, ATT_SMEM>>>(qs, ks, vs, g, ats);

    // 5. Output projection: [65536,768] @ [768,256] -> d_out (BM=64, no tail)
    gemm_mma<64><<<dim3(2, NROWS / 64), 256, NSTAGE * (64 * 128 + 16384)>>>(
        ats, Bo, 256, 0, out, nullptr, nullptr, nullptr, bo, nullptr);
}

// round 15
// speedup vs baseline: 1.2462x; 1.2462x over previous
#include <cuda_runtime.h>
#include <cuda_fp16.h>
#include <cstdint>
#include <math.h>

// Problem constants: B=1, n_seq=S=256, seq_len=L=256, c_m=256, H=8, ch=32, HC=256
#define S_DIM 256
#define L_DIM 256
#define C_DIM 256
#define HC_DIM 256
#define NH 8
#define CH 32
#define NROWS (S_DIM * L_DIM)  // 65536

// ---------------------------------------------------------------------------
// Scratch (device globals per allocation rules). fp16 hi/lo split layouts.
// ---------------------------------------------------------------------------
__device__ __align__(16) __half g_mn_split[NROWS * 512];   // [row][hi256|lo256]
__device__ __align__(16) __half g_att_split[NROWS * 512];
// Q/K/V attention-tile layout: [(l*8+h)][s][64] rows = [hi32|lo32] fp16
__device__ __align__(16) __half g_qs[NROWS * 512];
__device__ __align__(16) __half g_ks[NROWS * 512];
__device__ __align__(16) __half g_vs[NROWS * 512];
__device__ __align__(16) float g_g[NROWS * HC_DIM];
// B operands: single-rounded fp16 hi only (2-term scheme), K=256 rows
__device__ __align__(16) __half g_Bqkvg[256 * 1024];       // cols: q|k|v|g
__device__ __align__(16) __half g_Bo[256 * 256];

// ---------------------------------------------------------------------------
// Helpers
// ---------------------------------------------------------------------------
__device__ __forceinline__ uint32_t smem_u32(const void* p) {
    uint32_t a;
    asm("{ .reg .u64 t; cvta.to.shared.u64 t, %1; cvt.u32.u64 %0, t; }"
        : "=r"(a) : "l"(p));
    return a;
}

#define SWZ(o) ((o) ^ (((o) >> 3) & 0x70))

__device__ __forceinline__ void cp_async16(uint32_t saddr, const void* gptr) {
    asm volatile("cp.async.cg.shared.global [%0], [%1], 16;"
                 :: "r"(saddr), "l"(__cvta_generic_to_global(gptr)) : "memory");
}
#define CP_COMMIT() asm volatile("cp.async.commit_group;" ::: "memory")
#define CP_WAITG(n) asm volatile("cp.async.wait_group %0;" :: "n"(n) : "memory")

__device__ __forceinline__ void ldsm4(uint32_t* r, uint32_t addr) {
    asm volatile("ldmatrix.sync.aligned.m8n8.x4.shared.b16 {%0,%1,%2,%3}, [%4];"
                 : "=r"(r[0]), "=r"(r[1]), "=r"(r[2]), "=r"(r[3]) : "r"(addr));
}
__device__ __forceinline__ void ldsm4t(uint32_t* r, uint32_t addr) {
    asm volatile("ldmatrix.sync.aligned.m8n8.x4.trans.shared.b16 {%0,%1,%2,%3}, [%4];"
                 : "=r"(r[0]), "=r"(r[1]), "=r"(r[2]), "=r"(r[3]) : "r"(addr));
}
__device__ __forceinline__ void mma_f16(float* c, const uint32_t* a,
                                        uint32_t b0, uint32_t b1) {
    asm volatile(
        "mma.sync.aligned.m16n8k16.row.col.f32.f16.f16.f32 "
        "{%0,%1,%2,%3}, {%4,%5,%6,%7}, {%8,%9}, {%0,%1,%2,%3};"
        : "+f"(c[0]), "+f"(c[1]), "+f"(c[2]), "+f"(c[3])
        : "r"(a[0]), "r"(a[1]), "r"(a[2]), "r"(a[3]), "r"(b0), "r"(b1));
}

// fp32 pair -> fp16 hi/lo split (packed f16x2)
__device__ __forceinline__ void split2h(float a, float b, uint32_t& h, uint32_t& l) {
    uint32_t hb;
    asm("cvt.rn.f16x2.f32 %0, %1, %2;" : "=r"(hb) : "f"(b), "f"(a));
    const __half2 hh = *reinterpret_cast<const __half2*>(&hb);
    const float2 f = __half22float2(hh);
    uint32_t lo;
    asm("cvt.rn.f16x2.f32 %0, %1, %2;" : "=r"(lo) : "f"(b - f.y), "f"(a - f.x));
    h = hb;
    l = lo;
}

// ---------------------------------------------------------------------------
// LayerNorm -> split fp16 [row][512]. One warp per row.
// ---------------------------------------------------------------------------
__global__ __launch_bounds__(256) void ln_kernel(
    const float* __restrict__ m, const float* __restrict__ w,
    const float* __restrict__ b, __half* __restrict__ osplit)
{
    const int warp = threadIdx.x >> 5;
    const int lane = threadIdx.x & 31;
    const int row  = blockIdx.x * 8 + warp;

    const float4* x4 = (const float4*)(m + (size_t)row * C_DIM);
    float4 v0 = x4[lane * 2 + 0];
    float4 v1 = x4[lane * 2 + 1];

    float s1 = (v0.x + v0.y) + (v0.z + v0.w) + (v1.x + v1.y) + (v1.z + v1.w);
    float s2 = v0.x * v0.x + v0.y * v0.y + v0.z * v0.z + v0.w * v0.w
             + v1.x * v1.x + v1.y * v1.y + v1.z * v1.z + v1.w * v1.w;
    #pragma unroll
    for (int o = 16; o > 0; o >>= 1) {
        s1 += __shfl_xor_sync(0xffffffffu, s1, o);
        s2 += __shfl_xor_sync(0xffffffffu, s2, o);
    }
    const float mu  = s1 * (1.0f / 256.0f);
    const float var = s2 * (1.0f / 256.0f) - mu * mu;
    const float rs  = rsqrtf(var + 1e-5f);

    const float4* w4 = (const float4*)w;
    const float4* b4 = (const float4*)b;
    float4 w0 = w4[lane * 2 + 0], w1 = w4[lane * 2 + 1];
    float4 b0 = b4[lane * 2 + 0], b1 = b4[lane * 2 + 1];

    float r[8];
    r[0] = (v0.x - mu) * rs * w0.x + b0.x;
    r[1] = (v0.y - mu) * rs * w0.y + b0.y;
    r[2] = (v0.z - mu) * rs * w0.z + b0.z;
    r[3] = (v0.w - mu) * rs * w0.w + b0.w;
    r[4] = (v1.x - mu) * rs * w1.x + b1.x;
    r[5] = (v1.y - mu) * rs * w1.y + b1.y;
    r[6] = (v1.z - mu) * rs * w1.z + b1.z;
    r[7] = (v1.w - mu) * rs * w1.w + b1.w;

    uint4 H, L;
    split2h(r[0], r[1], H.x, L.x);
    split2h(r[2], r[3], H.y, L.y);
    split2h(r[4], r[5], H.z, L.z);
    split2h(r[6], r[7], H.w, L.w);
    const size_t ofs = (size_t)row * 512 + lane * 8;
    *(uint4*)(osplit + ofs)       = H;
    *(uint4*)(osplit + ofs + 256) = L;
}

// ---------------------------------------------------------------------------
// Weight prep: single-rounded fp16 B (hi only), transposed-free [k][n].
// ---------------------------------------------------------------------------
__global__ __launch_bounds__(256) void wconv_kernel(
    const float* __restrict__ w0, const float* __restrict__ w1,
    const float* __restrict__ w2, const float* __restrict__ w3,
    const float* __restrict__ w4,
    __half* __restrict__ Bqkvg, __half* __restrict__ Bo)
{
    const float* ws[5] = {w0, w1, w2, w3, w4};
    const int k   = blockIdx.x;        // 0..255
    const int wi  = blockIdx.y;        // 0..4
    const int n   = threadIdx.x;       // 0..255
    const __half v = __float2half_rn(ws[wi][k * 256 + n]);
    if (wi < 4) Bqkvg[(size_t)k * 1024 + wi * 256 + n] = v;
    else        Bo[(size_t)k * 256 + n] = v;
}

// ---------------------------------------------------------------------------
// fp16 2-term GEMM via mma.sync: C = (Ah + Al) @ Bh, K_ext = 512.
// A physical [row][512] = [hi|lo]; B physical [256][Nb], rows reused for
// kb 4..7 via (kb & 3). 128x128 tile, 256 thr — R11-proven config.
// ---------------------------------------------------------------------------
#define STAGE_BYTES 32768
#define NSTAGE 3
#define GEMM_SMEM (NSTAGE * STAGE_BYTES)
#define NKB 8

__device__ __forceinline__ void ld_chunk(
    uint32_t sbase, const __half* __restrict__ A,
    const __half* __restrict__ B, int Nb,
    size_t row0, int n0, int kb, int tid)
{
    const int a_off = kb * 64;
    #pragma unroll
    for (int t = 0; t < 4; t++) {
        const int i = tid + t * 256;
        const int r = i >> 3, c8 = i & 7;
        cp_async16(sbase + SWZ((uint32_t)(r * 128 + c8 * 16)),
                   A + (row0 + r) * 512 + a_off + c8 * 8);
    }
    const uint32_t bbase = sbase + 16384;
    const int b_row0 = (kb & 3) * 64;
    #pragma unroll
    for (int t = 0; t < 4; t++) {
        const int i = tid + t * 256;
        const int k = i >> 4, u = i & 15;
        const uint32_t sub = (u >= 8) ? 8192u : 0u;
        cp_async16(bbase + sub + SWZ((uint32_t)(k * 128 + (u & 7) * 16)),
                   B + (size_t)(b_row0 + k) * Nb + n0 + u * 8);
    }
}

__global__ __launch_bounds__(256, 2) void gemm_mma(
    const __half* __restrict__ A, const __half* __restrict__ B,
    int Nb, int qkv_mode,
    void* C0, void* C1, void* C2, void* C3,
    const float* bias0, const float* bias3)
{
    extern __shared__ char smem[];
    const uint32_t sb = smem_u32(smem);
    const int tid  = threadIdx.x;
    const int warp = tid >> 5, lane = tid & 31;
    const int wm = (warp >> 2) * 64;
    const int wn = (warp & 3) * 32;
    const size_t row0 = (size_t)blockIdx.y * 128;
    const int n0 = blockIdx.x * 128;

    #pragma unroll
    for (int s = 0; s < 3; s++) {
        ld_chunk(sb + s * STAGE_BYTES, A, B, Nb, row0, n0, s, tid);
        CP_COMMIT();
    }

    float acc[4][4][4];
    #pragma unroll
    for (int i = 0; i < 4; i++)
        #pragma unroll
        for (int j = 0; j < 4; j++)
            #pragma unroll
            for (int x = 0; x < 4; x++) acc[i][j][x] = 0.0f;

    const int lr  = lane & 15;
    const int lh  = lane >> 4;
    const uint32_t bsub = (wn >= 64) ? 8192u : 0u;
    const int wn2 = wn & 63;

    const uint32_t mix = (uint32_t)((lr & 7) << 4);
    uint32_t abase[4];
    #pragma unroll
    for (int i = 0; i < 4; i++)
        abase[i] = (uint32_t)((wm + i * 16 + lr) * 128)
                   + ((uint32_t)(lh * 16) ^ mix);
    uint32_t bbase[2];
    #pragma unroll
    for (int j2 = 0; j2 < 2; j2++)
        bbase[j2] = 16384u + bsub + (uint32_t)(lr * 128)
                    + ((uint32_t)(wn2 * 2 + j2 * 32 + lh * 16) ^ mix);

    #pragma unroll 1
    for (int kb = 0; kb < NKB; kb++) {
        CP_WAITG(2);
        __syncthreads();
        const int stg = kb % 3;
        const uint32_t sgb = sb + stg * STAGE_BYTES;

        #pragma unroll
        for (int kk = 0; kk < 4; kk++) {
            uint32_t a[4][4];
            #pragma unroll
            for (int i = 0; i < 4; i++)
                ldsm4(a[i], sgb + (abase[i] ^ (uint32_t)(kk * 32)));
            uint32_t bfr[2][4];
            #pragma unroll
            for (int j2 = 0; j2 < 2; j2++)
                ldsm4t(bfr[j2], sgb + bbase[j2] + (uint32_t)(kk * 2048));
            #pragma unroll
            for (int i = 0; i < 4; i++)
                #pragma unroll
                for (int j = 0; j < 4; j++)
                    mma_f16(acc[i][j], a[i],
                            bfr[j >> 1][(j & 1) * 2], bfr[j >> 1][(j & 1) * 2 + 1]);
        }
        __syncthreads();
        if (kb + 3 < NKB) ld_chunk(sb + stg * STAGE_BYTES, A, B, Nb, row0, n0, kb + 3, tid);
        CP_COMMIT();
    }

    const int buf = (n0 >> 8) & 3;
    const int colbase = (n0 & 255) + wn + (lane & 3) * 2;

    if (qkv_mode && buf < 3) {
        __half* Cq = (__half*)((buf == 0) ? C0 : (buf == 1) ? C1 : C2);
        const float qsc = (buf == 0) ? 0.17677669529663689f * 1.44269504088896f
                                     : 1.0f;
        #pragma unroll
        for (int i = 0; i < 4; i++) {
            const int r0 = (int)row0 + wm + i * 16 + (lane >> 2);
            #pragma unroll
            for (int j = 0; j < 4; j++) {
                const int col = colbase + j * 8;
                const int hh = col >> 5, cc = col & 31;
                #pragma unroll
                for (int rr = 0; rr < 2; rr++) {
                    const int r = r0 + rr * 8;
                    const int s = r >> 8, ll = r & 255;
                    const size_t dst = ((size_t)(ll * 8 + hh) * 256 + s) * 64 + cc;
                    uint32_t H, L;
                    split2h(acc[i][j][rr * 2] * qsc, acc[i][j][rr * 2 + 1] * qsc,
                            H, L);
                    *(uint32_t*)(Cq + dst)      = H;
                    *(uint32_t*)(Cq + dst + 32) = L;
                }
            }
        }
    } else {
        float* C = (float*)((qkv_mode) ? C3 : C0);
        const float* bias = (qkv_mode) ? bias3 : bias0;
        #pragma unroll
        for (int i = 0; i < 4; i++) {
            const size_t r0 = row0 + wm + i * 16 + (lane >> 2);
            #pragma unroll
            for (int j = 0; j < 4; j++) {
                const int col = colbase + j * 8;
                float bx = 0.f, by = 0.f;
                if (bias) { bx = bias[col]; by = bias[col + 1]; }
                float2 v0 = make_float2(acc[i][j][0] + bx, acc[i][j][1] + by);
                float2 v1 = make_float2(acc[i][j][2] + bx, acc[i][j][3] + by);
                *(float2*)(C + r0 * 256 + col)       = v0;
                *(float2*)(C + (r0 + 8) * 256 + col) = v1;
            }
        }
    }
}

// ---------------------------------------------------------------------------
// Tensor-core flash attention per (l,h) tile, 512 threads / 16 warps,
// 2 CTAs/SM. fp16 3-term split (error ~2^-22, negligible). R10 structure.
//   s' = h*32 + l/8 ; l' = (l%8)*32 + s/8 ; c' = (s%8)*32 + c
// ---------------------------------------------------------------------------
#define ATT_SMEM (3 * 32768)

__global__ __launch_bounds__(512, 2) void attn_mma_kernel(
    const __half* __restrict__ Qg, const __half* __restrict__ Kg,
    const __half* __restrict__ Vg, const float* __restrict__ Gg,
    __half* __restrict__ Osplit)
{
    extern __shared__ char smem[];
    const uint32_t sb = smem_u32(smem);
    const uint32_t QS = sb, KS = sb + 32768, VS = sb + 65536;

    const int tile = blockIdx.x;
    const int l = tile >> 3, h = tile & 7;
    const int tid = threadIdx.x;
    const size_t gbase0 = (size_t)tile * 256 * 64;

    #pragma unroll
    for (int t = 0; t < 4; t++) {
        const int idx = t * 512 + tid;
        const int r = idx >> 3, j = idx & 7;
        const uint32_t so = SWZ((uint32_t)(r * 128 + j * 16));
        const size_t go = gbase0 + (size_t)r * 64 + j * 8;
        cp_async16(QS + so, Qg + go);
        cp_async16(KS + so, Kg + go);
        cp_async16(VS + so, Vg + go);
    }
    CP_COMMIT();
    CP_WAITG(0);
    __syncthreads();

    const int warp = tid >> 5, lane = tid & 31;
    const int s0 = warp * 16;
    const int lr = lane & 15, lh = lane >> 4;

    uint32_t qh[2][4], ql[2][4];
    #pragma unroll
    for (int kk = 0; kk < 2; kk++) {
        const uint32_t rowb = (uint32_t)(s0 + lr) * 128;
        ldsm4(qh[kk], QS + SWZ(rowb + (kk * 16 + lh * 8) * 2));
        ldsm4(ql[kk], QS + SWZ(rowb + (32 + kk * 16 + lh * 8) * 2));
    }

    const int klr = (lane & 7) + ((lane >> 4) << 3);
    const uint32_t mix = (uint32_t)((lane & 7) << 4);
    const uint32_t kcolb = (uint32_t)(((lane >> 3) & 1) * 16);
    uint32_t kaddr[2], vaddr[2];
    #pragma unroll
    for (int c = 0; c < 2; c++) {
        kaddr[c] = KS + (uint32_t)(klr * 128) + ((kcolb + c * 32) ^ mix);
        vaddr[c] = VS + (uint32_t)(lr * 128)
                   + (((uint32_t)(lh * 16) + c * 32) ^ mix);
    }

    float o[4][4];
    #pragma unroll
    for (int j = 0; j < 4; j++)
        #pragma unroll
        for (int x = 0; x < 4; x++) o[j][x] = 0.0f;
    float sm[2] = {0.f, 0.f};

    auto S_compute = [&](int gt, float s[2][4]) {
        const uint32_t gg = (uint32_t)(gt * 2048);
        uint32_t kh[2][4], kl[2][4];
        ldsm4(kh[0], kaddr[0] + gg);
        ldsm4(kh[1], kaddr[1] + gg);
        ldsm4(kl[0], (kaddr[0] + gg) ^ 64u);
        ldsm4(kl[1], (kaddr[1] + gg) ^ 64u);
        #pragma unroll
        for (int x = 0; x < 4; x++) { s[0][x] = 0.f; s[1][x] = 0.f; }
        #pragma unroll
        for (int ch = 0; ch < 2; ch++) {
            mma_f16(s[0], qh[ch], kh[ch][0], kh[ch][1]);
            mma_f16(s[1], qh[ch], kh[ch][2], kh[ch][3]);
            mma_f16(s[0], ql[ch], kh[ch][0], kh[ch][1]);
            mma_f16(s[1], ql[ch], kh[ch][2], kh[ch][3]);
            mma_f16(s[0], qh[ch], kl[ch][0], kl[ch][1]);
            mma_f16(s[1], qh[ch], kl[ch][2], kl[ch][3]);
        }
    };

    auto PV_compute = [&](int gt, float s[2][4]) {
        #pragma unroll
        for (int tgt = 0; tgt < 2; tgt++) {
            #pragma unroll
            for (int x = 0; x < 4; x++) s[tgt][x] = exp2f(s[tgt][x]);
        }
        sm[0] += (s[0][0] + s[0][1]) + (s[1][0] + s[1][1]);
        sm[1] += (s[0][2] + s[0][3]) + (s[1][2] + s[1][3]);

        uint32_t ah[4], al[4];
        split2h(s[0][0], s[0][1], ah[0], al[0]);
        split2h(s[0][2], s[0][3], ah[1], al[1]);
        split2h(s[1][0], s[1][1], ah[2], al[2]);
        split2h(s[1][2], s[1][3], ah[3], al[3]);

        const uint32_t gg = (uint32_t)(gt * 2048);
        uint32_t vh[2][4], vl[2][4];
        ldsm4t(vh[0], vaddr[0] + gg);
        ldsm4t(vh[1], vaddr[1] + gg);
        ldsm4t(vl[0], (vaddr[0] + gg) ^ 64u);
        ldsm4t(vl[1], (vaddr[1] + gg) ^ 64u);
        #pragma unroll
        for (int j = 0; j < 4; j++) {
            const int j2 = j >> 1, jj = (j & 1) * 2;
            mma_f16(o[j], ah, vh[j2][jj], vh[j2][jj + 1]);
            mma_f16(o[j], al, vh[j2][jj], vh[j2][jj + 1]);
            mma_f16(o[j], ah, vl[j2][jj], vl[j2][jj + 1]);
        }
    };

    float s_a[2][4], s_b[2][4];
    S_compute(0, s_a);
    #pragma unroll
    for (int gt = 0; gt < 16; gt += 2) {
        if (gt + 1 < 16) S_compute(gt + 1, s_b);
        PV_compute(gt, s_a);
        if (gt + 2 < 16) S_compute(gt + 2, s_a);
        if (gt + 1 < 16) PV_compute(gt + 1, s_b);
    }

    // ---- epilogue: normalize, gate, scramble, store split fp16 ----
    const int i_o = h * 32 + (l >> 3);
    #pragma unroll
    for (int rr = 0; rr < 2; rr++) {
        float v = sm[rr];
        v += __shfl_xor_sync(0xffffffffu, v, 1);
        v += __shfl_xor_sync(0xffffffffu, v, 2);
        const float inv = 1.0f / v;
        const int s = s0 + (lane >> 2) + rr * 8;
        const int j_o = ((l & 7) << 5) + (s >> 3);
        const int k_o = (s & 7) << 5;
        const size_t gb = ((size_t)i_o * 256 + j_o) * 256 + k_o;
        const size_t ob = ((size_t)i_o * 256 + j_o) * 512 + k_o;
        #pragma unroll
        for (int j = 0; j < 4; j++) {
            const int c = j * 8 + (lane & 3) * 2;
            const float2 gg = *(const float2*)(Gg + gb + c);
            const float w0 = o[j][rr * 2] * inv
                             / (1.0f + exp2f(-gg.x * 1.44269504088896f));
            const float w1 = o[j][rr * 2 + 1] * inv
                             / (1.0f + exp2f(-gg.y * 1.44269504088896f));
            uint32_t H, L;
            split2h(w0, w1, H, L);
            *(uint32_t*)(Osplit + ob + c)       = H;
            *(uint32_t*)(Osplit + ob + 256 + c) = L;
        }
    }
}

// ---------------------------------------------------------------------------
extern "C" void kernel_launch(void* const* d_in, const int* in_sizes, int n_in,
                              void* d_out, int out_size)
{
    const float* m    = (const float*)d_in[0];
    const float* ln_w = (const float*)d_in[1];
    const float* ln_b = (const float*)d_in[2];
    const float* wq   = (const float*)d_in[3];
    const float* wk   = (const float*)d_in[4];
    const float* wv   = (const float*)d_in[5];
    const float* wg   = (const float*)d_in[6];
    const float* bg   = (const float*)d_in[7];
    const float* wo   = (const float*)d_in[8];
    const float* bo   = (const float*)d_in[9];
    float* out = (float*)d_out;

    __half *mns, *ats, *Bq, *Bo, *qs, *ks, *vs;
    float *g;
    cudaGetSymbolAddress((void**)&mns, g_mn_split);
    cudaGetSymbolAddress((void**)&ats, g_att_split);
    cudaGetSymbolAddress((void**)&qs,  g_qs);
    cudaGetSymbolAddress((void**)&ks,  g_ks);
    cudaGetSymbolAddress((void**)&vs,  g_vs);
    cudaGetSymbolAddress((void**)&g,   g_g);
    cudaGetSymbolAddress((void**)&Bq,  g_Bqkvg);
    cudaGetSymbolAddress((void**)&Bo,  g_Bo);

    cudaFuncSetAttribute(gemm_mma,
                         cudaFuncAttributeMaxDynamicSharedMemorySize, GEMM_SMEM);
    cudaFuncSetAttribute(attn_mma_kernel,
                         cudaFuncAttributeMaxDynamicSharedMemorySize, ATT_SMEM);

    // 1. LayerNorm -> split fp16
    ln_kernel<<<NROWS / 8, 256>>>(m, ln_w, ln_b, mns);

    // 2. Weight prep (single-rounded fp16)
    wconv_kernel<<<dim3(256, 5), 256>>>(wq, wk, wv, wg, wo, Bq, Bo);

    // 3. Fused Q/K/V/G projection: 2-term fp16, K_ext=512
    gemm_mma<<<dim3(8, NROWS / 128), 256, GEMM_SMEM>>>(
        mns, Bq, 1024, 1, qs, ks, vs, g, nullptr, bg);

    // 4. Tensor-core flash attention (2 CTA/SM, fp16 3-term) + gate + scramble
    attn_mma_kernel<<<L_DIM * NH, 512, ATT_SMEM>>>(qs, ks, vs, g, ats);

    // 5. Output projection: 2-term fp16 -> d_out (+bo)
    gemm_mma<<<dim3(2, NROWS / 128), 256, GEMM_SMEM>>>(
        ats, Bo, 256, 0, out, nullptr, nullptr, nullptr, bo, nullptr);
}

// round 16
// speedup vs baseline: 1.3298x; 1.0671x over previous
#include <cuda_runtime.h>
#include <cuda_fp16.h>
#include <cstdint>
#include <math.h>

// Problem constants: B=1, n_seq=S=256, seq_len=L=256, c_m=256, H=8, ch=32, HC=256
#define S_DIM 256
#define L_DIM 256
#define C_DIM 256
#define HC_DIM 256
#define NH 8
#define CH 32
#define NROWS (S_DIM * L_DIM)  // 65536

// ---------------------------------------------------------------------------
// Scratch (device globals per allocation rules). fp16 hi/lo split layouts.
// ---------------------------------------------------------------------------
__device__ __align__(16) __half g_mn_split[NROWS * 512];   // [row][hi256|lo256]
__device__ __align__(16) __half g_att_split[NROWS * 512];
// Q/K/V attention-tile layout: [(l*8+h)][s][64] rows = [hi32|lo32] fp16
__device__ __align__(16) __half g_qs[NROWS * 512];
__device__ __align__(16) __half g_ks[NROWS * 512];
__device__ __align__(16) __half g_vs[NROWS * 512];
__device__ __align__(16) float g_g[NROWS * HC_DIM];
// B operands: single-rounded fp16 hi only (2-term scheme), K=256 rows
__device__ __align__(16) __half g_Bqkvg[256 * 1024];       // cols: q|k|v|g
__device__ __align__(16) __half g_Bo[256 * 256];

// ---------------------------------------------------------------------------
// Helpers
// ---------------------------------------------------------------------------
__device__ __forceinline__ uint32_t smem_u32(const void* p) {
    uint32_t a;
    asm("{ .reg .u64 t; cvta.to.shared.u64 t, %1; cvt.u32.u64 %0, t; }"
        : "=r"(a) : "l"(p));
    return a;
}

#define SWZ(o) ((o) ^ (((o) >> 3) & 0x70))

__device__ __forceinline__ void cp_async16(uint32_t saddr, const void* gptr) {
    asm volatile("cp.async.cg.shared.global [%0], [%1], 16;"
                 :: "r"(saddr), "l"(__cvta_generic_to_global(gptr)) : "memory");
}
#define CP_COMMIT() asm volatile("cp.async.commit_group;" ::: "memory")
#define CP_WAITG(n) asm volatile("cp.async.wait_group %0;" :: "n"(n) : "memory")

__device__ __forceinline__ void ldsm4(uint32_t* r, uint32_t addr) {
    asm volatile("ldmatrix.sync.aligned.m8n8.x4.shared.b16 {%0,%1,%2,%3}, [%4];"
                 : "=r"(r[0]), "=r"(r[1]), "=r"(r[2]), "=r"(r[3]) : "r"(addr));
}
__device__ __forceinline__ void ldsm4t(uint32_t* r, uint32_t addr) {
    asm volatile("ldmatrix.sync.aligned.m8n8.x4.trans.shared.b16 {%0,%1,%2,%3}, [%4];"
                 : "=r"(r[0]), "=r"(r[1]), "=r"(r[2]), "=r"(r[3]) : "r"(addr));
}
__device__ __forceinline__ void mma_f16(float* c, const uint32_t* a,
                                        uint32_t b0, uint32_t b1) {
    asm volatile(
        "mma.sync.aligned.m16n8k16.row.col.f32.f16.f16.f32 "
        "{%0,%1,%2,%3}, {%4,%5,%6,%7}, {%8,%9}, {%0,%1,%2,%3};"
        : "+f"(c[0]), "+f"(c[1]), "+f"(c[2]), "+f"(c[3])
        : "r"(a[0]), "r"(a[1]), "r"(a[2]), "r"(a[3]), "r"(b0), "r"(b1));
}

// fp32 pair -> fp16 hi/lo split (packed f16x2)
__device__ __forceinline__ void split2h(float a, float b, uint32_t& h, uint32_t& l) {
    uint32_t hb;
    asm("cvt.rn.f16x2.f32 %0, %1, %2;" : "=r"(hb) : "f"(b), "f"(a));
    const __half2 hh = *reinterpret_cast<const __half2*>(&hb);
    const float2 f = __half22float2(hh);
    uint32_t lo;
    asm("cvt.rn.f16x2.f32 %0, %1, %2;" : "=r"(lo) : "f"(b - f.y), "f"(a - f.x));
    h = hb;
    l = lo;
}

// fp32 pair -> packed f16x2 (hi only, no residual)
__device__ __forceinline__ uint32_t pack2h(float a, float b) {
    uint32_t r;
    asm("cvt.rn.f16x2.f32 %0, %1, %2;" : "=r"(r) : "f"(b), "f"(a));
    return r;
}

// ---------------------------------------------------------------------------
// LayerNorm -> split fp16 [row][512]. One warp per row.
// ---------------------------------------------------------------------------
__global__ __launch_bounds__(256) void ln_kernel(
    const float* __restrict__ m, const float* __restrict__ w,
    const float* __restrict__ b, __half* __restrict__ osplit)
{
    const int warp = threadIdx.x >> 5;
    const int lane = threadIdx.x & 31;
    const int row  = blockIdx.x * 8 + warp;

    const float4* x4 = (const float4*)(m + (size_t)row * C_DIM);
    float4 v0 = x4[lane * 2 + 0];
    float4 v1 = x4[lane * 2 + 1];

    float s1 = (v0.x + v0.y) + (v0.z + v0.w) + (v1.x + v1.y) + (v1.z + v1.w);
    float s2 = v0.x * v0.x + v0.y * v0.y + v0.z * v0.z + v0.w * v0.w
             + v1.x * v1.x + v1.y * v1.y + v1.z * v1.z + v1.w * v1.w;
    #pragma unroll
    for (int o = 16; o > 0; o >>= 1) {
        s1 += __shfl_xor_sync(0xffffffffu, s1, o);
        s2 += __shfl_xor_sync(0xffffffffu, s2, o);
    }
    const float mu  = s1 * (1.0f / 256.0f);
    const float var = s2 * (1.0f / 256.0f) - mu * mu;
    const float rs  = rsqrtf(var + 1e-5f);

    const float4* w4 = (const float4*)w;
    const float4* b4 = (const float4*)b;
    float4 w0 = w4[lane * 2 + 0], w1 = w4[lane * 2 + 1];
    float4 b0 = b4[lane * 2 + 0], b1 = b4[lane * 2 + 1];

    float r[8];
    r[0] = (v0.x - mu) * rs * w0.x + b0.x;
    r[1] = (v0.y - mu) * rs * w0.y + b0.y;
    r[2] = (v0.z - mu) * rs * w0.z + b0.z;
    r[3] = (v0.w - mu) * rs * w0.w + b0.w;
    r[4] = (v1.x - mu) * rs * w1.x + b1.x;
    r[5] = (v1.y - mu) * rs * w1.y + b1.y;
    r[6] = (v1.z - mu) * rs * w1.z + b1.z;
    r[7] = (v1.w - mu) * rs * w1.w + b1.w;

    uint4 H, L;
    split2h(r[0], r[1], H.x, L.x);
    split2h(r[2], r[3], H.y, L.y);
    split2h(r[4], r[5], H.z, L.z);
    split2h(r[6], r[7], H.w, L.w);
    const size_t ofs = (size_t)row * 512 + lane * 8;
    *(uint4*)(osplit + ofs)       = H;
    *(uint4*)(osplit + ofs + 256) = L;
}

// ---------------------------------------------------------------------------
// Weight prep: single-rounded fp16 B (hi only), [k][n].
// ---------------------------------------------------------------------------
__global__ __launch_bounds__(256) void wconv_kernel(
    const float* __restrict__ w0, const float* __restrict__ w1,
    const float* __restrict__ w2, const float* __restrict__ w3,
    const float* __restrict__ w4,
    __half* __restrict__ Bqkvg, __half* __restrict__ Bo)
{
    const float* ws[5] = {w0, w1, w2, w3, w4};
    const int k   = blockIdx.x;        // 0..255
    const int wi  = blockIdx.y;        // 0..4
    const int n   = threadIdx.x;       // 0..255
    const __half v = __float2half_rn(ws[wi][k * 256 + n]);
    if (wi < 4) Bqkvg[(size_t)k * 1024 + wi * 256 + n] = v;
    else        Bo[(size_t)k * 256 + n] = v;
}

// ---------------------------------------------------------------------------
// fp16 2-term GEMM via mma.sync: C = (Ah + Al) @ Bh, K_ext = 512.
// 128x128 tile, 256 thr, minBlocks=2 — proven config, unchanged from R15.
// ---------------------------------------------------------------------------
#define STAGE_BYTES 32768
#define NSTAGE 3
#define GEMM_SMEM (NSTAGE * STAGE_BYTES)
#define NKB 8

__device__ __forceinline__ void ld_chunk(
    uint32_t sbase, const __half* __restrict__ A,
    const __half* __restrict__ B, int Nb,
    size_t row0, int n0, int kb, int tid)
{
    const int a_off = kb * 64;
    #pragma unroll
    for (int t = 0; t < 4; t++) {
        const int i = tid + t * 256;
        const int r = i >> 3, c8 = i & 7;
        cp_async16(sbase + SWZ((uint32_t)(r * 128 + c8 * 16)),
                   A + (row0 + r) * 512 + a_off + c8 * 8);
    }
    const uint32_t bbase = sbase + 16384;
    const int b_row0 = (kb & 3) * 64;
    #pragma unroll
    for (int t = 0; t < 4; t++) {
        const int i = tid + t * 256;
        const int k = i >> 4, u = i & 15;
        const uint32_t sub = (u >= 8) ? 8192u : 0u;
        cp_async16(bbase + sub + SWZ((uint32_t)(k * 128 + (u & 7) * 16)),
                   B + (size_t)(b_row0 + k) * Nb + n0 + u * 8);
    }
}

__global__ __launch_bounds__(256, 2) void gemm_mma(
    const __half* __restrict__ A, const __half* __restrict__ B,
    int Nb, int qkv_mode,
    void* C0, void* C1, void* C2, void* C3,
    const float* bias0, const float* bias3)
{
    extern __shared__ char smem[];
    const uint32_t sb = smem_u32(smem);
    const int tid  = threadIdx.x;
    const int warp = tid >> 5, lane = tid & 31;
    const int wm = (warp >> 2) * 64;
    const int wn = (warp & 3) * 32;
    const size_t row0 = (size_t)blockIdx.y * 128;
    const int n0 = blockIdx.x * 128;

    #pragma unroll
    for (int s = 0; s < 3; s++) {
        ld_chunk(sb + s * STAGE_BYTES, A, B, Nb, row0, n0, s, tid);
        CP_COMMIT();
    }

    float acc[4][4][4];
    #pragma unroll
    for (int i = 0; i < 4; i++)
        #pragma unroll
        for (int j = 0; j < 4; j++)
            #pragma unroll
            for (int x = 0; x < 4; x++) acc[i][j][x] = 0.0f;

    const int lr  = lane & 15;
    const int lh  = lane >> 4;
    const uint32_t bsub = (wn >= 64) ? 8192u : 0u;
    const int wn2 = wn & 63;

    const uint32_t mix = (uint32_t)((lr & 7) << 4);
    uint32_t abase[4];
    #pragma unroll
    for (int i = 0; i < 4; i++)
        abase[i] = (uint32_t)((wm + i * 16 + lr) * 128)
                   + ((uint32_t)(lh * 16) ^ mix);
    uint32_t bbase[2];
    #pragma unroll
    for (int j2 = 0; j2 < 2; j2++)
        bbase[j2] = 16384u + bsub + (uint32_t)(lr * 128)
                    + ((uint32_t)(wn2 * 2 + j2 * 32 + lh * 16) ^ mix);

    #pragma unroll 1
    for (int kb = 0; kb < NKB; kb++) {
        CP_WAITG(2);
        __syncthreads();
        const int stg = kb % 3;
        const uint32_t sgb = sb + stg * STAGE_BYTES;

        #pragma unroll
        for (int kk = 0; kk < 4; kk++) {
            uint32_t a[4][4];
            #pragma unroll
            for (int i = 0; i < 4; i++)
                ldsm4(a[i], sgb + (abase[i] ^ (uint32_t)(kk * 32)));
            uint32_t bfr[2][4];
            #pragma unroll
            for (int j2 = 0; j2 < 2; j2++)
                ldsm4t(bfr[j2], sgb + bbase[j2] + (uint32_t)(kk * 2048));
            #pragma unroll
            for (int i = 0; i < 4; i++)
                #pragma unroll
                for (int j = 0; j < 4; j++)
                    mma_f16(acc[i][j], a[i],
                            bfr[j >> 1][(j & 1) * 2], bfr[j >> 1][(j & 1) * 2 + 1]);
        }
        __syncthreads();
        if (kb + 3 < NKB) ld_chunk(sb + stg * STAGE_BYTES, A, B, Nb, row0, n0, kb + 3, tid);
        CP_COMMIT();
    }

    const int buf = (n0 >> 8) & 3;
    const int colbase = (n0 & 255) + wn + (lane & 3) * 2;

    if (qkv_mode && buf < 3) {
        __half* Cq = (__half*)((buf == 0) ? C0 : (buf == 1) ? C1 : C2);
        const float qsc = (buf == 0) ? 0.17677669529663689f * 1.44269504088896f
                                     : 1.0f;
        #pragma unroll
        for (int i = 0; i < 4; i++) {
            const int r0 = (int)row0 + wm + i * 16 + (lane >> 2);
            #pragma unroll
            for (int j = 0; j < 4; j++) {
                const int col = colbase + j * 8;
                const int hh = col >> 5, cc = col & 31;
                #pragma unroll
                for (int rr = 0; rr < 2; rr++) {
                    const int r = r0 + rr * 8;
                    const int s = r >> 8, ll = r & 255;
                    const size_t dst = ((size_t)(ll * 8 + hh) * 256 + s) * 64 + cc;
                    uint32_t H, L;
                    split2h(acc[i][j][rr * 2] * qsc, acc[i][j][rr * 2 + 1] * qsc,
                            H, L);
                    *(uint32_t*)(Cq + dst)      = H;
                    *(uint32_t*)(Cq + dst + 32) = L;
                }
            }
        }
    } else {
        float* C = (float*)((qkv_mode) ? C3 : C0);
        const float* bias = (qkv_mode) ? bias3 : bias0;
        #pragma unroll
        for (int i = 0; i < 4; i++) {
            const size_t r0 = row0 + wm + i * 16 + (lane >> 2);
            #pragma unroll
            for (int j = 0; j < 4; j++) {
                const int col = colbase + j * 8;
                float bx = 0.f, by = 0.f;
                if (bias) { bx = bias[col]; by = bias[col + 1]; }
                float2 v0 = make_float2(acc[i][j][0] + bx, acc[i][j][1] + by);
                float2 v1 = make_float2(acc[i][j][2] + bx, acc[i][j][3] + by);
                *(float2*)(C + r0 * 256 + col)       = v0;
                *(float2*)(C + (r0 + 8) * 256 + col) = v1;
            }
        }
    }
}

// ---------------------------------------------------------------------------
// Tensor-core flash attention per (l,h) tile, 512 threads / 16 warps,
// 2 CTAs/SM. fp16: S = 3-term (logit precision), PV = 1-term Ph·Vh
// (convex combination; dropped lo-terms ~1e-4 each on output).
//   s' = h*32 + l/8 ; l' = (l%8)*32 + s/8 ; c' = (s%8)*32 + c
// ---------------------------------------------------------------------------
#define ATT_SMEM (3 * 32768)

__global__ __launch_bounds__(512, 2) void attn_mma_kernel(
    const __half* __restrict__ Qg, const __half* __restrict__ Kg,
    const __half* __restrict__ Vg, const float* __restrict__ Gg,
    __half* __restrict__ Osplit)
{
    extern __shared__ char smem[];
    const uint32_t sb = smem_u32(smem);
    const uint32_t QS = sb, KS = sb + 32768, VS = sb + 65536;

    const int tile = blockIdx.x;
    const int l = tile >> 3, h = tile & 7;
    const int tid = threadIdx.x;
    const size_t gbase0 = (size_t)tile * 256 * 64;

    // Q, K full tiles (32KB each); V hi-half only (16KB).
    #pragma unroll
    for (int t = 0; t < 4; t++) {
        const int idx = t * 512 + tid;
        const int r = idx >> 3, j = idx & 7;
        const uint32_t so = SWZ((uint32_t)(r * 128 + j * 16));
        const size_t go = gbase0 + (size_t)r * 64 + j * 8;
        cp_async16(QS + so, Qg + go);
        cp_async16(KS + so, Kg + go);
    }
    #pragma unroll
    for (int t = 0; t < 2; t++) {
        const int idx = t * 512 + tid;
        const int r = idx >> 2, j = idx & 3;   // j covers hi 64B of the row
        cp_async16(VS + SWZ((uint32_t)(r * 128 + j * 16)),
                   Vg + gbase0 + (size_t)r * 64 + j * 8);
    }
    CP_COMMIT();
    CP_WAITG(0);
    __syncthreads();

    const int warp = tid >> 5, lane = tid & 31;
    const int s0 = warp * 16;
    const int lr = lane & 15, lh = lane >> 4;

    uint32_t qh[2][4], ql[2][4];
    #pragma unroll
    for (int kk = 0; kk < 2; kk++) {
        const uint32_t rowb = (uint32_t)(s0 + lr) * 128;
        ldsm4(qh[kk], QS + SWZ(rowb + (kk * 16 + lh * 8) * 2));
        ldsm4(ql[kk], QS + SWZ(rowb + (32 + kk * 16 + lh * 8) * 2));
    }

    const int klr = (lane & 7) + ((lane >> 4) << 3);
    const uint32_t mix = (uint32_t)((lane & 7) << 4);
    const uint32_t kcolb = (uint32_t)(((lane >> 3) & 1) * 16);
    uint32_t kaddr[2], vaddr[2];
    #pragma unroll
    for (int c = 0; c < 2; c++) {
        kaddr[c] = KS + (uint32_t)(klr * 128) + ((kcolb + c * 32) ^ mix);
        vaddr[c] = VS + (uint32_t)(lr * 128)
                   + (((uint32_t)(lh * 16) + c * 32) ^ mix);
    }

    float o[4][4];
    #pragma unroll
    for (int j = 0; j < 4; j++)
        #pragma unroll
        for (int x = 0; x < 4; x++) o[j][x] = 0.0f;
    float sm[2] = {0.f, 0.f};

    auto S_compute = [&](int gt, float s[2][4]) {
        const uint32_t gg = (uint32_t)(gt * 2048);
        uint32_t kh[2][4], kl[2][4];
        ldsm4(kh[0], kaddr[0] + gg);
        ldsm4(kh[1], kaddr[1] + gg);
        ldsm4(kl[0], (kaddr[0] + gg) ^ 64u);
        ldsm4(kl[1], (kaddr[1] + gg) ^ 64u);
        #pragma unroll
        for (int x = 0; x < 4; x++) { s[0][x] = 0.f; s[1][x] = 0.f; }
        #pragma unroll
        for (int ch = 0; ch < 2; ch++) {
            mma_f16(s[0], qh[ch], kh[ch][0], kh[ch][1]);
            mma_f16(s[1], qh[ch], kh[ch][2], kh[ch][3]);
            mma_f16(s[0], ql[ch], kh[ch][0], kh[ch][1]);
            mma_f16(s[1], ql[ch], kh[ch][2], kh[ch][3]);
            mma_f16(s[0], qh[ch], kl[ch][0], kl[ch][1]);
            mma_f16(s[1], qh[ch], kl[ch][2], kl[ch][3]);
        }
    };

    auto PV_compute = [&](int gt, float s[2][4]) {
        #pragma unroll
        for (int tgt = 0; tgt < 2; tgt++) {
            #pragma unroll
            for (int x = 0; x < 4; x++) s[tgt][x] = exp2f(s[tgt][x]);
        }
        sm[0] += (s[0][0] + s[0][1]) + (s[1][0] + s[1][1]);
        sm[1] += (s[0][2] + s[0][3]) + (s[1][2] + s[1][3]);

        uint32_t ah[4];
        ah[0] = pack2h(s[0][0], s[0][1]);
        ah[1] = pack2h(s[0][2], s[0][3]);
        ah[2] = pack2h(s[1][0], s[1][1]);
        ah[3] = pack2h(s[1][2], s[1][3]);

        const uint32_t gg = (uint32_t)(gt * 2048);
        uint32_t vh[2][4];
        ldsm4t(vh[0], vaddr[0] + gg);
        ldsm4t(vh[1], vaddr[1] + gg);
        #pragma unroll
        for (int j = 0; j < 4; j++) {
            const int j2 = j >> 1, jj = (j & 1) * 2;
            mma_f16(o[j], ah, vh[j2][jj], vh[j2][jj + 1]);
        }
    };

    float s_a[2][4], s_b[2][4];
    S_compute(0, s_a);
    #pragma unroll
    for (int gt = 0; gt < 16; gt += 2) {
        if (gt + 1 < 16) S_compute(gt + 1, s_b);
        PV_compute(gt, s_a);
        if (gt + 2 < 16) S_compute(gt + 2, s_a);
        if (gt + 1 < 16) PV_compute(gt + 1, s_b);
    }

    // ---- epilogue: normalize, gate, scramble, store split fp16 ----
    const int i_o = h * 32 + (l >> 3);
    #pragma unroll
    for (int rr = 0; rr < 2; rr++) {
        float v = sm[rr];
        v += __shfl_xor_sync(0xffffffffu, v, 1);
        v += __shfl_xor_sync(0xffffffffu, v, 2);
        const float inv = 1.0f / v;
        const int s = s0 + (lane >> 2) + rr * 8;
        const int j_o = ((l & 7) << 5) + (s >> 3);
        const int k_o = (s & 7) << 5;
        const size_t gb = ((size_t)i_o * 256 + j_o) * 256 + k_o;
        const size_t ob = ((size_t)i_o * 256 + j_o) * 512 + k_o;
        #pragma unroll
        for (int j = 0; j < 4; j++) {
            const int c = j * 8 + (lane & 3) * 2;
            const float2 gg = *(const float2*)(Gg + gb + c);
            const float w0 = o[j][rr * 2] * inv
                             / (1.0f + exp2f(-gg.x * 1.44269504088896f));
            const float w1 = o[j][rr * 2 + 1] * inv
                             / (1.0f + exp2f(-gg.y * 1.44269504088896f));
            uint32_t H, L;
            split2h(w0, w1, H, L);
            *(uint32_t*)(Osplit + ob + c)       = H;
            *(uint32_t*)(Osplit + ob + 256 + c) = L;
        }
    }
}

// ---------------------------------------------------------------------------
extern "C" void kernel_launch(void* const* d_in, const int* in_sizes, int n_in,
                              void* d_out, int out_size)
{
    const float* m    = (const float*)d_in[0];
    const float* ln_w = (const float*)d_in[1];
    const float* ln_b = (const float*)d_in[2];
    const float* wq   = (const float*)d_in[3];
    const float* wk   = (const float*)d_in[4];
    const float* wv   = (const float*)d_in[5];
    const float* wg   = (const float*)d_in[6];
    const float* bg   = (const float*)d_in[7];
    const float* wo   = (const float*)d_in[8];
    const float* bo   = (const float*)d_in[9];
    float* out = (float*)d_out;

    __half *mns, *ats, *Bq, *Bo, *qs, *ks, *vs;
    float *g;
    cudaGetSymbolAddress((void**)&mns, g_mn_split);
    cudaGetSymbolAddress((void**)&ats, g_att_split);
    cudaGetSymbolAddress((void**)&qs,  g_qs);
    cudaGetSymbolAddress((void**)&ks,  g_ks);
    cudaGetSymbolAddress((void**)&vs,  g_vs);
    cudaGetSymbolAddress((void**)&g,   g_g);
    cudaGetSymbolAddress((void**)&Bq,  g_Bqkvg);
    cudaGetSymbolAddress((void**)&Bo,  g_Bo);

    cudaFuncSetAttribute(gemm_mma,
                         cudaFuncAttributeMaxDynamicSharedMemorySize, GEMM_SMEM);
    cudaFuncSetAttribute(attn_mma_kernel,
                         cudaFuncAttributeMaxDynamicSharedMemorySize, ATT_SMEM);

    // 1. LayerNorm -> split fp16
    ln_kernel<<<NROWS / 8, 256>>>(m, ln_w, ln_b, mns);

    // 2. Weight prep (single-rounded fp16)
    wconv_kernel<<<dim3(256, 5), 256>>>(wq, wk, wv, wg, wo, Bq, Bo);

    // 3. Fused Q/K/V/G projection: 2-term fp16, K_ext=512
    gemm_mma<<<dim3(8, NROWS / 128), 256, GEMM_SMEM>>>(
        mns, Bq, 1024, 1, qs, ks, vs, g, nullptr, bg);

    // 4. Tensor-core flash attention (2 CTA/SM, S 3-term / PV 1-term)
    attn_mma_kernel<<<L_DIM * NH, 512, ATT_SMEM>>>(qs, ks, vs, g, ats);

    // 5. Output projection: 2-term fp16 -> d_out (+bo)
    gemm_mma<<<dim3(2, NROWS / 128), 256, GEMM_SMEM>>>(
        ats, Bo, 256, 0, out, nullptr, nullptr, nullptr, bo, nullptr);
}

// round 17
// speedup vs baseline: 1.5130x; 1.1378x over previous
#include <cuda_runtime.h>
#include <cuda_fp16.h>
#include <cstdint>
#include <math.h>

// Problem constants: B=1, n_seq=S=256, seq_len=L=256, c_m=256, H=8, ch=32, HC=256
#define S_DIM 256
#define L_DIM 256
#define C_DIM 256
#define HC_DIM 256
#define NH 8
#define CH 32
#define NROWS (S_DIM * L_DIM)  // 65536

// ---------------------------------------------------------------------------
// Scratch (device globals per allocation rules). fp16 hi/lo split layouts.
// ---------------------------------------------------------------------------
__device__ __align__(16) __half g_mn_split[NROWS * 512];   // [row][hi256|lo256]
__device__ __align__(16) __half g_att[NROWS * 256];        // hi only (1-term A)
// Q/K/V attention-tile layout: [(l*8+h)][s][64] rows = [hi32|lo32] fp16
__device__ __align__(16) __half g_qs[NROWS * 512];
__device__ __align__(16) __half g_ks[NROWS * 512];
__device__ __align__(16) __half g_vs[NROWS * 512];
__device__ __align__(16) float g_g[NROWS * HC_DIM];
// B operands: single-rounded fp16 (hi only), K=256 rows
__device__ __align__(16) __half g_Bqkvg[256 * 1024];       // cols: q|k|v|g
__device__ __align__(16) __half g_Bo[256 * 256];

// ---------------------------------------------------------------------------
// Helpers
// ---------------------------------------------------------------------------
__device__ __forceinline__ uint32_t smem_u32(const void* p) {
    uint32_t a;
    asm("{ .reg .u64 t; cvta.to.shared.u64 t, %1; cvt.u32.u64 %0, t; }"
        : "=r"(a) : "l"(p));
    return a;
}

#define SWZ(o) ((o) ^ (((o) >> 3) & 0x70))

__device__ __forceinline__ void cp_async16(uint32_t saddr, const void* gptr) {
    asm volatile("cp.async.cg.shared.global [%0], [%1], 16;"
                 :: "r"(saddr), "l"(__cvta_generic_to_global(gptr)) : "memory");
}
#define CP_COMMIT() asm volatile("cp.async.commit_group;" ::: "memory")
#define CP_WAITG(n) asm volatile("cp.async.wait_group %0;" :: "n"(n) : "memory")

__device__ __forceinline__ void ldsm4(uint32_t* r, uint32_t addr) {
    asm volatile("ldmatrix.sync.aligned.m8n8.x4.shared.b16 {%0,%1,%2,%3}, [%4];"
                 : "=r"(r[0]), "=r"(r[1]), "=r"(r[2]), "=r"(r[3]) : "r"(addr));
}
__device__ __forceinline__ void ldsm4t(uint32_t* r, uint32_t addr) {
    asm volatile("ldmatrix.sync.aligned.m8n8.x4.trans.shared.b16 {%0,%1,%2,%3}, [%4];"
                 : "=r"(r[0]), "=r"(r[1]), "=r"(r[2]), "=r"(r[3]) : "r"(addr));
}
__device__ __forceinline__ void mma_f16(float* c, const uint32_t* a,
                                        uint32_t b0, uint32_t b1) {
    asm volatile(
        "mma.sync.aligned.m16n8k16.row.col.f32.f16.f16.f32 "
        "{%0,%1,%2,%3}, {%4,%5,%6,%7}, {%8,%9}, {%0,%1,%2,%3};"
        : "+f"(c[0]), "+f"(c[1]), "+f"(c[2]), "+f"(c[3])
        : "r"(a[0]), "r"(a[1]), "r"(a[2]), "r"(a[3]), "r"(b0), "r"(b1));
}

// fp32 pair -> fp16 hi/lo split (packed f16x2)
__device__ __forceinline__ void split2h(float a, float b, uint32_t& h, uint32_t& l) {
    uint32_t hb;
    asm("cvt.rn.f16x2.f32 %0, %1, %2;" : "=r"(hb) : "f"(b), "f"(a));
    const __half2 hh = *reinterpret_cast<const __half2*>(&hb);
    const float2 f = __half22float2(hh);
    uint32_t lo;
    asm("cvt.rn.f16x2.f32 %0, %1, %2;" : "=r"(lo) : "f"(b - f.y), "f"(a - f.x));
    h = hb;
    l = lo;
}

// fp32 pair -> packed f16x2 (hi only)
__device__ __forceinline__ uint32_t pack2h(float a, float b) {
    uint32_t r;
    asm("cvt.rn.f16x2.f32 %0, %1, %2;" : "=r"(r) : "f"(b), "f"(a));
    return r;
}

// ---------------------------------------------------------------------------
// LayerNorm -> split fp16 [row][512]. One warp per row.
// ---------------------------------------------------------------------------
__global__ __launch_bounds__(256) void ln_kernel(
    const float* __restrict__ m, const float* __restrict__ w,
    const float* __restrict__ b, __half* __restrict__ osplit)
{
    const int warp = threadIdx.x >> 5;
    const int lane = threadIdx.x & 31;
    const int row  = blockIdx.x * 8 + warp;

    const float4* x4 = (const float4*)(m + (size_t)row * C_DIM);
    float4 v0 = x4[lane * 2 + 0];
    float4 v1 = x4[lane * 2 + 1];

    float s1 = (v0.x + v0.y) + (v0.z + v0.w) + (v1.x + v1.y) + (v1.z + v1.w);
    float s2 = v0.x * v0.x + v0.y * v0.y + v0.z * v0.z + v0.w * v0.w
             + v1.x * v1.x + v1.y * v1.y + v1.z * v1.z + v1.w * v1.w;
    #pragma unroll
    for (int o = 16; o > 0; o >>= 1) {
        s1 += __shfl_xor_sync(0xffffffffu, s1, o);
        s2 += __shfl_xor_sync(0xffffffffu, s2, o);
    }
    const float mu  = s1 * (1.0f / 256.0f);
    const float var = s2 * (1.0f / 256.0f) - mu * mu;
    const float rs  = rsqrtf(var + 1e-5f);

    const float4* w4 = (const float4*)w;
    const float4* b4 = (const float4*)b;
    float4 w0 = w4[lane * 2 + 0], w1 = w4[lane * 2 + 1];
    float4 b0 = b4[lane * 2 + 0], b1 = b4[lane * 2 + 1];

    float r[8];
    r[0] = (v0.x - mu) * rs * w0.x + b0.x;
    r[1] = (v0.y - mu) * rs * w0.y + b0.y;
    r[2] = (v0.z - mu) * rs * w0.z + b0.z;
    r[3] = (v0.w - mu) * rs * w0.w + b0.w;
    r[4] = (v1.x - mu) * rs * w1.x + b1.x;
    r[5] = (v1.y - mu) * rs * w1.y + b1.y;
    r[6] = (v1.z - mu) * rs * w1.z + b1.z;
    r[7] = (v1.w - mu) * rs * w1.w + b1.w;

    uint4 H, L;
    split2h(r[0], r[1], H.x, L.x);
    split2h(r[2], r[3], H.y, L.y);
    split2h(r[4], r[5], H.z, L.z);
    split2h(r[6], r[7], H.w, L.w);
    const size_t ofs = (size_t)row * 512 + lane * 8;
    *(uint4*)(osplit + ofs)       = H;
    *(uint4*)(osplit + ofs + 256) = L;
}

// ---------------------------------------------------------------------------
// Weight prep: single-rounded fp16 B (hi only), [k][n].
// ---------------------------------------------------------------------------
__global__ __launch_bounds__(256) void wconv_kernel(
    const float* __restrict__ w0, const float* __restrict__ w1,
    const float* __restrict__ w2, const float* __restrict__ w3,
    const float* __restrict__ w4,
    __half* __restrict__ Bqkvg, __half* __restrict__ Bo)
{
    const float* ws[5] = {w0, w1, w2, w3, w4};
    const int k   = blockIdx.x;        // 0..255
    const int wi  = blockIdx.y;        // 0..4
    const int n   = threadIdx.x;       // 0..255
    const __half v = __float2half_rn(ws[wi][k * 256 + n]);
    if (wi < 4) Bqkvg[(size_t)k * 1024 + wi * 256 + n] = v;
    else        Bo[(size_t)k * 256 + n] = v;
}

// ---------------------------------------------------------------------------
// fp16 GEMM via mma.sync: C = A_terms @ Bh.
// nkb0=8 (2-term: Ah kb0-3, Al kb4-7) or 4 (1-term Ah). In qkv_mode, V/G
// column blocks (buf>=2) auto-reduce to 1-term (contractive error paths).
// Astride = A row stride in elements (512 split / 256 hi-only).
// 128x128 tile, 256 thr, minBlocks=2 — proven config.
// ---------------------------------------------------------------------------
#define STAGE_BYTES 32768
#define NSTAGE 3
#define GEMM_SMEM (NSTAGE * STAGE_BYTES)

__device__ __forceinline__ void ld_chunk(
    uint32_t sbase, const __half* __restrict__ A, int Astride,
    const __half* __restrict__ B, int Nb,
    size_t row0, int n0, int kb, int tid)
{
    const int a_off = kb * 64;
    #pragma unroll
    for (int t = 0; t < 4; t++) {
        const int i = tid + t * 256;
        const int r = i >> 3, c8 = i & 7;
        cp_async16(sbase + SWZ((uint32_t)(r * 128 + c8 * 16)),
                   A + (row0 + r) * Astride + a_off + c8 * 8);
    }
    const uint32_t bbase = sbase + 16384;
    const int b_row0 = (kb & 3) * 64;
    #pragma unroll
    for (int t = 0; t < 4; t++) {
        const int i = tid + t * 256;
        const int k = i >> 4, u = i & 15;
        const uint32_t sub = (u >= 8) ? 8192u : 0u;
        cp_async16(bbase + sub + SWZ((uint32_t)(k * 128 + (u & 7) * 16)),
                   B + (size_t)(b_row0 + k) * Nb + n0 + u * 8);
    }
}

__global__ __launch_bounds__(256, 2) void gemm_mma(
    const __half* __restrict__ A, int Astride,
    const __half* __restrict__ B, int Nb, int qkv_mode, int nkb0,
    void* C0, void* C1, void* C2, void* C3,
    const float* bias0, const float* bias3)
{
    extern __shared__ char smem[];
    const uint32_t sb = smem_u32(smem);
    const int tid  = threadIdx.x;
    const int warp = tid >> 5, lane = tid & 31;
    const int wm = (warp >> 2) * 64;
    const int wn = (warp & 3) * 32;
    const size_t row0 = (size_t)blockIdx.y * 128;
    const int n0 = blockIdx.x * 128;
    const int buf = (n0 >> 8) & 3;
    const int nkb = (qkv_mode && buf >= 2) ? 4 : nkb0;

    #pragma unroll
    for (int s = 0; s < 3; s++) {
        ld_chunk(sb + s * STAGE_BYTES, A, Astride, B, Nb, row0, n0, s, tid);
        CP_COMMIT();
    }

    float acc[4][4][4];
    #pragma unroll
    for (int i = 0; i < 4; i++)
        #pragma unroll
        for (int j = 0; j < 4; j++)
            #pragma unroll
            for (int x = 0; x < 4; x++) acc[i][j][x] = 0.0f;

    const int lr  = lane & 15;
    const int lh  = lane >> 4;
    const uint32_t bsub = (wn >= 64) ? 8192u : 0u;
    const int wn2 = wn & 63;

    const uint32_t mix = (uint32_t)((lr & 7) << 4);
    uint32_t abase[4];
    #pragma unroll
    for (int i = 0; i < 4; i++)
        abase[i] = (uint32_t)((wm + i * 16 + lr) * 128)
                   + ((uint32_t)(lh * 16) ^ mix);
    uint32_t bbase[2];
    #pragma unroll
    for (int j2 = 0; j2 < 2; j2++)
        bbase[j2] = 16384u + bsub + (uint32_t)(lr * 128)
                    + ((uint32_t)(wn2 * 2 + j2 * 32 + lh * 16) ^ mix);

    #pragma unroll 1
    for (int kb = 0; kb < nkb; kb++) {
        CP_WAITG(2);
        __syncthreads();
        const int stg = kb % 3;
        const uint32_t sgb = sb + stg * STAGE_BYTES;

        #pragma unroll
        for (int kk = 0; kk < 4; kk++) {
            uint32_t a[4][4];
            #pragma unroll
            for (int i = 0; i < 4; i++)
                ldsm4(a[i], sgb + (abase[i] ^ (uint32_t)(kk * 32)));
            uint32_t bfr[2][4];
            #pragma unroll
            for (int j2 = 0; j2 < 2; j2++)
                ldsm4t(bfr[j2], sgb + bbase[j2] + (uint32_t)(kk * 2048));
            #pragma unroll
            for (int i = 0; i < 4; i++)
                #pragma unroll
                for (int j = 0; j < 4; j++)
                    mma_f16(acc[i][j], a[i],
                            bfr[j >> 1][(j & 1) * 2], bfr[j >> 1][(j & 1) * 2 + 1]);
        }
        __syncthreads();
        if (kb + 3 < nkb) ld_chunk(sb + stg * STAGE_BYTES, A, Astride, B, Nb,
                                   row0, n0, kb + 3, tid);
        CP_COMMIT();
    }

    const int colbase = (n0 & 255) + wn + (lane & 3) * 2;

    if (qkv_mode && buf < 3) {
        __half* Cq = (__half*)((buf == 0) ? C0 : (buf == 1) ? C1 : C2);
        const float qsc = (buf == 0) ? 0.17677669529663689f * 1.44269504088896f
                                     : 1.0f;
        #pragma unroll
        for (int i = 0; i < 4; i++) {
            const int r0 = (int)row0 + wm + i * 16 + (lane >> 2);
            #pragma unroll
            for (int j = 0; j < 4; j++) {
                const int col = colbase + j * 8;
                const int hh = col >> 5, cc = col & 31;
                #pragma unroll
                for (int rr = 0; rr < 2; rr++) {
                    const int r = r0 + rr * 8;
                    const int s = r >> 8, ll = r & 255;
                    const size_t dst = ((size_t)(ll * 8 + hh) * 256 + s) * 64 + cc;
                    uint32_t H, L;
                    split2h(acc[i][j][rr * 2] * qsc, acc[i][j][rr * 2 + 1] * qsc,
                            H, L);
                    *(uint32_t*)(Cq + dst) = H;
                    if (buf < 2)                       // V-lo never read
                        *(uint32_t*)(Cq + dst + 32) = L;
                }
            }
        }
    } else {
        float* C = (float*)((qkv_mode) ? C3 : C0);
        const float* bias = (qkv_mode) ? bias3 : bias0;
        #pragma unroll
        for (int i = 0; i < 4; i++) {
            const size_t r0 = row0 + wm + i * 16 + (lane >> 2);
            #pragma unroll
            for (int j = 0; j < 4; j++) {
                const int col = colbase + j * 8;
                float bx = 0.f, by = 0.f;
                if (bias) { bx = bias[col]; by = bias[col + 1]; }
                float2 v0 = make_float2(acc[i][j][0] + bx, acc[i][j][1] + by);
                float2 v1 = make_float2(acc[i][j][2] + bx, acc[i][j][3] + by);
                *(float2*)(C + r0 * 256 + col)       = v0;
                *(float2*)(C + (r0 + 8) * 256 + col) = v1;
            }
        }
    }
}

// ---------------------------------------------------------------------------
// Tensor-core flash attention per (l,h) tile, 512 threads / 16 warps,
// 2 CTAs/SM. fp16: S = 3-term, PV = 1-term. Output: hi-only fp16 [row][256]
// (out-proj is 1-term). R16 structure otherwise.
//   s' = h*32 + l/8 ; l' = (l%8)*32 + s/8 ; c' = (s%8)*32 + c
// ---------------------------------------------------------------------------
#define ATT_SMEM (3 * 32768)

__global__ __launch_bounds__(512, 2) void attn_mma_kernel(
    const __half* __restrict__ Qg, const __half* __restrict__ Kg,
    const __half* __restrict__ Vg, const float* __restrict__ Gg,
    __half* __restrict__ Oh)
{
    extern __shared__ char smem[];
    const uint32_t sb = smem_u32(smem);
    const uint32_t QS = sb, KS = sb + 32768, VS = sb + 65536;

    const int tile = blockIdx.x;
    const int l = tile >> 3, h = tile & 7;
    const int tid = threadIdx.x;
    const size_t gbase0 = (size_t)tile * 256 * 64;

    // Q, K full tiles (32KB each); V hi-half only (16KB).
    #pragma unroll
    for (int t = 0; t < 4; t++) {
        const int idx = t * 512 + tid;
        const int r = idx >> 3, j = idx & 7;
        const uint32_t so = SWZ((uint32_t)(r * 128 + j * 16));
        const size_t go = gbase0 + (size_t)r * 64 + j * 8;
        cp_async16(QS + so, Qg + go);
        cp_async16(KS + so, Kg + go);
    }
    #pragma unroll
    for (int t = 0; t < 2; t++) {
        const int idx = t * 512 + tid;
        const int r = idx >> 2, j = idx & 3;
        cp_async16(VS + SWZ((uint32_t)(r * 128 + j * 16)),
                   Vg + gbase0 + (size_t)r * 64 + j * 8);
    }
    CP_COMMIT();
    CP_WAITG(0);
    __syncthreads();

    const int warp = tid >> 5, lane = tid & 31;
    const int s0 = warp * 16;
    const int lr = lane & 15, lh = lane >> 4;

    uint32_t qh[2][4], ql[2][4];
    #pragma unroll
    for (int kk = 0; kk < 2; kk++) {
        const uint32_t rowb = (uint32_t)(s0 + lr) * 128;
        ldsm4(qh[kk], QS + SWZ(rowb + (kk * 16 + lh * 8) * 2));
        ldsm4(ql[kk], QS + SWZ(rowb + (32 + kk * 16 + lh * 8) * 2));
    }

    const int klr = (lane & 7) + ((lane >> 4) << 3);
    const uint32_t mix = (uint32_t)((lane & 7) << 4);
    const uint32_t kcolb = (uint32_t)(((lane >> 3) & 1) * 16);
    uint32_t kaddr[2], vaddr[2];
    #pragma unroll
    for (int c = 0; c < 2; c++) {
        kaddr[c] = KS + (uint32_t)(klr * 128) + ((kcolb + c * 32) ^ mix);
        vaddr[c] = VS + (uint32_t)(lr * 128)
                   + (((uint32_t)(lh * 16) + c * 32) ^ mix);
    }

    float o[4][4];
    #pragma unroll
    for (int j = 0; j < 4; j++)
        #pragma unroll
        for (int x = 0; x < 4; x++) o[j][x] = 0.0f;
    float sm[2] = {0.f, 0.f};

    auto S_compute = [&](int gt, float s[2][4]) {
        const uint32_t gg = (uint32_t)(gt * 2048);
        uint32_t kh[2][4], kl[2][4];
        ldsm4(kh[0], kaddr[0] + gg);
        ldsm4(kh[1], kaddr[1] + gg);
        ldsm4(kl[0], (kaddr[0] + gg) ^ 64u);
        ldsm4(kl[1], (kaddr[1] + gg) ^ 64u);
        #pragma unroll
        for (int x = 0; x < 4; x++) { s[0][x] = 0.f; s[1][x] = 0.f; }
        #pragma unroll
        for (int ch = 0; ch < 2; ch++) {
            mma_f16(s[0], qh[ch], kh[ch][0], kh[ch][1]);
            mma_f16(s[1], qh[ch], kh[ch][2], kh[ch][3]);
            mma_f16(s[0], ql[ch], kh[ch][0], kh[ch][1]);
            mma_f16(s[1], ql[ch], kh[ch][2], kh[ch][3]);
            mma_f16(s[0], qh[ch], kl[ch][0], kl[ch][1]);
            mma_f16(s[1], qh[ch], kl[ch][2], kl[ch][3]);
        }
    };

    auto PV_compute = [&](int gt, float s[2][4]) {
        #pragma unroll
        for (int tgt = 0; tgt < 2; tgt++) {
            #pragma unroll
            for (int x = 0; x < 4; x++) s[tgt][x] = exp2f(s[tgt][x]);
        }
        sm[0] += (s[0][0] + s[0][1]) + (s[1][0] + s[1][1]);
        sm[1] += (s[0][2] + s[0][3]) + (s[1][2] + s[1][3]);

        uint32_t ah[4];
        ah[0] = pack2h(s[0][0], s[0][1]);
        ah[1] = pack2h(s[0][2], s[0][3]);
        ah[2] = pack2h(s[1][0], s[1][1]);
        ah[3] = pack2h(s[1][2], s[1][3]);

        const uint32_t gg = (uint32_t)(gt * 2048);
        uint32_t vh[2][4];
        ldsm4t(vh[0], vaddr[0] + gg);
        ldsm4t(vh[1], vaddr[1] + gg);
        #pragma unroll
        for (int j = 0; j < 4; j++) {
            const int j2 = j >> 1, jj = (j & 1) * 2;
            mma_f16(o[j], ah, vh[j2][jj], vh[j2][jj + 1]);
        }
    };

    float s_a[2][4], s_b[2][4];
    S_compute(0, s_a);
    #pragma unroll
    for (int gt = 0; gt < 16; gt += 2) {
        if (gt + 1 < 16) S_compute(gt + 1, s_b);
        PV_compute(gt, s_a);
        if (gt + 2 < 16) S_compute(gt + 2, s_a);
        if (gt + 1 < 16) PV_compute(gt + 1, s_b);
    }

    // ---- epilogue: normalize, gate, scramble, store fp16 (hi only) ----
    const int i_o = h * 32 + (l >> 3);
    #pragma unroll
    for (int rr = 0; rr < 2; rr++) {
        float v = sm[rr];
        v += __shfl_xor_sync(0xffffffffu, v, 1);
        v += __shfl_xor_sync(0xffffffffu, v, 2);
        const float inv = 1.0f / v;
        const int s = s0 + (lane >> 2) + rr * 8;
        const int j_o = ((l & 7) << 5) + (s >> 3);
        const int k_o = (s & 7) << 5;
        const size_t gb = ((size_t)i_o * 256 + j_o) * 256 + k_o;
        #pragma unroll
        for (int j = 0; j < 4; j++) {
            const int c = j * 8 + (lane & 3) * 2;
            const float2 gg = *(const float2*)(Gg + gb + c);
            const float w0 = o[j][rr * 2] * inv
                             / (1.0f + exp2f(-gg.x * 1.44269504088896f));
            const float w1 = o[j][rr * 2 + 1] * inv
                             / (1.0f + exp2f(-gg.y * 1.44269504088896f));
            *(uint32_t*)(Oh + gb + c) = pack2h(w0, w1);
        }
    }
}

// ---------------------------------------------------------------------------
extern "C" void kernel_launch(void* const* d_in, const int* in_sizes, int n_in,
                              void* d_out, int out_size)
{
    const float* m    = (const float*)d_in[0];
    const float* ln_w = (const float*)d_in[1];
    const float* ln_b = (const float*)d_in[2];
    const float* wq   = (const float*)d_in[3];
    const float* wk   = (const float*)d_in[4];
    const float* wv   = (const float*)d_in[5];
    const float* wg   = (const float*)d_in[6];
    const float* bg   = (const float*)d_in[7];
    const float* wo   = (const float*)d_in[8];
    const float* bo   = (const float*)d_in[9];
    float* out = (float*)d_out;

    __half *mns, *ats, *Bq, *Bo, *qs, *ks, *vs;
    float *g;
    cudaGetSymbolAddress((void**)&mns, g_mn_split);
    cudaGetSymbolAddress((void**)&ats, g_att);
    cudaGetSymbolAddress((void**)&qs,  g_qs);
    cudaGetSymbolAddress((void**)&ks,  g_ks);
    cudaGetSymbolAddress((void**)&vs,  g_vs);
    cudaGetSymbolAddress((void**)&g,   g_g);
    cudaGetSymbolAddress((void**)&Bq,  g_Bqkvg);
    cudaGetSymbolAddress((void**)&Bo,  g_Bo);

    cudaFuncSetAttribute(gemm_mma,
                         cudaFuncAttributeMaxDynamicSharedMemorySize, GEMM_SMEM);
    cudaFuncSetAttribute(attn_mma_kernel,
                         cudaFuncAttributeMaxDynamicSharedMemorySize, ATT_SMEM);

    // 1. LayerNorm -> split fp16
    ln_kernel<<<NROWS / 8, 256>>>(m, ln_w, ln_b, mns);

    // 2. Weight prep (single-rounded fp16)
    wconv_kernel<<<dim3(256, 5), 256>>>(wq, wk, wv, wg, wo, Bq, Bo);

    // 3. Fused Q/K/V/G projection: Q/K 2-term, V/G 1-term fp16
    gemm_mma<<<dim3(8, NROWS / 128), 256, GEMM_SMEM>>>(
        mns, 512, Bq, 1024, 1, 8, qs, ks, vs, g, nullptr, bg);

    // 4. Tensor-core flash attention (2 CTA/SM) -> hi-only fp16
    attn_mma_kernel<<<L_DIM * NH, 512, ATT_SMEM>>>(qs, ks, vs, g, ats);

    // 5. Output projection: 1-term fp16 -> d_out (+bo)
    gemm_mma<<<dim3(2, NROWS / 128), 256, GEMM_SMEM>>>(
        ats, 256, Bo, 256, 0, 4, out, nullptr, nullptr, nullptr, bo, nullptr);
}